// round 12
// baseline (speedup 1.0000x reference)
#include <cuda_runtime.h>
#include <math.h>

#define Bsz   1024
#define Nn    32
#define SE    10
#define OOUT  5
#define IIN   6
#define GPB   16     // samples per block
#define TPB   512    // 16 warps = 4 quads; quad owns 4 samples
                     // quad warp (rowhalf,khalf): dims rowhalf*30+lane, K-half khalf

// ---- shared memory layout (float offsets; all listed bases 16B-aligned) ----
// Weight rows use stride 72: K-half0 @ +0 (30 floats), K-half1 @ +36 (30 floats)
#define S_WHH  0        // 180*72 = 12960
#define S_WIH  12960    // 12960
#define S_WF   25920    // 60*88 = 5280: h0@0, h1@36, zd@68
#define S_BIH  31200    // 180
#define S_BF   31380    // 60
#define S_HAS  31440    // 512
#define S_ZD   31952    // 320
#define S_H    32272    // 4 quads * 2 bufs * 4 samples * 72 = 2304
#define S_RHO  34576    // 16*72 = 1152
#define S_PART 35728    // 4 quads * 60 dims * 12 = 2880
#define SMEM_FLOATS 38608   // 154432 B -> 1 block/SM

// ---- device scratch ----
__device__ int   g_fcnt[Nn];
__device__ int   g_flist[Nn][Nn];
__device__ int   g_bcnt[Nn];
__device__ int   g_blist[Nn][Nn];
__device__ float g_rho_f[Nn * Bsz * 60];
__device__ float g_rho_b[Nn * Bsz * 60];
__device__ float g_af[Bsz * 60];
__device__ float g_ab[Bsz * 60];
__device__ float g_gi_f[Nn * Bsz * 180];   // gi cache incl. bih: [node][b][row]
__device__ float g_gi_b[Nn * Bsz * 180];

__device__ __forceinline__ void fma2(unsigned long long& a,
                                     unsigned long long b, unsigned long long c) {
    asm("fma.rn.f32x2 %0,%1,%2,%0;" : "+l"(a) : "l"(b), "l"(c));
}
__device__ __forceinline__ float red2(unsigned long long v) {
    float x, y;
    asm("mov.b64 {%0,%1},%2;" : "=f"(x), "=f"(y) : "l"(v));
    return x + y;
}
__device__ __forceinline__ float sigmf_(float x) {
    return __fdividef(1.0f, 1.0f + __expf(-x));
}
__device__ __forceinline__ float tanhsafe_(float x) {
    float a = fabsf(x);
    float e = __expf(-2.0f * a);
    float t = __fdividef(1.0f - e, 1.0f + e);
    return copysignf(t, x);
}
#define QUADBAR(id) asm volatile("bar.sync %0, %1;" :: "r"(id), "r"(128) : "memory")

// 3-gate half-K GEMV: w0 = row(dim d, gate0) + khalf offset; gate stride 4320.
// hb = input vector base (+khalf offset), sample stride 72. 30 floats per half.
__device__ __forceinline__ void gemv_half(const float* __restrict__ w0,
                                          const float* __restrict__ hb,
                                          float* p0, float* p1, float* p2) {
    unsigned long long A0[4] = {0,0,0,0}, A1[4] = {0,0,0,0}, A2[4] = {0,0,0,0};
    #pragma unroll
    for (int qq = 0; qq < 7; qq++) {
        const ulonglong2 a = *(const ulonglong2*)(w0 + 4 * qq);
        const ulonglong2 b = *(const ulonglong2*)(w0 + 4320 + 4 * qq);
        const ulonglong2 c = *(const ulonglong2*)(w0 + 8640 + 4 * qq);
        #pragma unroll
        for (int m = 0; m < 4; m++) {
            const ulonglong2 h = *(const ulonglong2*)(hb + m * 72 + 4 * qq);
            fma2(A0[m], a.x, h.x); fma2(A0[m], a.y, h.y);
            fma2(A1[m], b.x, h.x); fma2(A1[m], b.y, h.y);
            fma2(A2[m], c.x, h.x); fma2(A2[m], c.y, h.y);
        }
    }
    const unsigned long long at = *(const unsigned long long*)(w0 + 28);
    const unsigned long long bt = *(const unsigned long long*)(w0 + 4320 + 28);
    const unsigned long long ct = *(const unsigned long long*)(w0 + 8640 + 28);
    #pragma unroll
    for (int m = 0; m < 4; m++) {
        const unsigned long long ht = *(const unsigned long long*)(hb + m * 72 + 28);
        fma2(A0[m], at, ht); fma2(A1[m], bt, ht); fma2(A2[m], ct, ht);
    }
    #pragma unroll
    for (int m = 0; m < 4; m++) {
        p0[m] = red2(A0[m]); p1[m] = red2(A1[m]); p2[m] = red2(A2[m]);
    }
}

// ============================================================
// Prep: decode adj + build ordered edge lists
// ============================================================
__global__ void k_prep(const unsigned char* __restrict__ adj_raw) {
    __shared__ float sadj[Nn * Nn];
    __shared__ int s_gt1, s_off4;
    const int tid = threadIdx.x;
    if (tid == 0) { s_gt1 = 0; s_off4 = 0; }
    __syncthreads();
    int f_gt1 = 0, f_off4 = 0;
    for (int t = tid; t < Nn * Nn; t += blockDim.x) {
        unsigned char c = adj_raw[t];
        if (c > 1) f_gt1 = 1;
        if (c == 1 && (t & 3) != 0) f_off4 = 1;
    }
    if (f_gt1)  atomicOr(&s_gt1, 1);
    if (f_off4) atomicOr(&s_off4, 1);
    __syncthreads();
    const int mode = s_gt1 ? 1 : (s_off4 ? 0 : 2);
    for (int e = tid; e < Nn * Nn; e += blockDim.x) {
        float v;
        if (mode == 1)      v = ((const float*)adj_raw)[e];
        else if (mode == 2) v = (float)(((const int*)adj_raw)[e]);
        else                v = (float)adj_raw[e];
        sadj[e] = v;
    }
    __syncthreads();
    if (tid < Nn) {
        const int i = tid; int c = 0;
        for (int j = 0; j < Nn; j++)
            if (sadj[j * Nn + i] != 0.0f) g_flist[i][c++] = j;
        g_fcnt[i] = c;
    } else if (tid < 2 * Nn) {
        const int i = tid - Nn; int c = 0;
        for (int j = Nn - 1; j >= 0; j--)
            if (sadj[i * Nn + j] != 0.0f) g_blist[i][c++] = j;
        g_bcnt[i] = c;
    }
}

// ============================================================
// Main scan: 128 blocks (64 fwd, 64 bwd), 16 samples each.
// Quad (4 warps) owns 4 samples; warp = (rowhalf, khalf).
// khalf1 writes partials to smem; khalf0 combines + pointwise.
// 16 warps/SM = 4/SMSP for stall coverage.
// ============================================================
__global__ void __launch_bounds__(TPB) k_scan(
    const float* __restrict__ has, const float* __restrict__ z, const float* __restrict__ dz,
    const float* __restrict__ Wih_f, const float* __restrict__ Whh_f,
    const float* __restrict__ bih_f, const float* __restrict__ bhh_f,
    const float* __restrict__ Wih_b, const float* __restrict__ Whh_b,
    const float* __restrict__ bih_b, const float* __restrict__ bhh_b,
    const float* __restrict__ Wfp, const float* __restrict__ bfp,
    const float* __restrict__ Wbp, const float* __restrict__ bbp)
{
    extern __shared__ __align__(16) float sm[];
    const int dir = blockIdx.x >> 6;
    const int b0  = (blockIdx.x & 63) * GPB;
    const float* Wih = dir ? Wih_b : Wih_f;
    const float* Whh = dir ? Whh_b : Whh_f;
    const float* bih = dir ? bih_b : bih_f;
    const float* bhh = dir ? bhh_b : bhh_f;
    const float* Wp  = dir ? Wbp   : Wfp;
    const float* bp  = dir ? bbp   : bfp;
    float* grho = dir ? g_rho_b : g_rho_f;
    float* gic  = dir ? g_gi_b  : g_gi_f;

    const int  tid     = threadIdx.x;
    const int  warp    = tid >> 5;
    const int  lane    = tid & 31;
    const int  quad    = warp >> 2;       // 0..3
    const int  w2      = warp & 3;
    const int  rowhalf = w2 & 1;          // dims [rowhalf*30, +30)
    const int  khalf   = w2 >> 1;         // K-half
    const int  sb      = quad * 4;
    const int  barid   = 1 + quad;
    const bool act     = lane < 30;
    const int  d       = rowhalf * 30 + lane;
    const int  dsl     = d + (d >= 30 ? 6 : 0);   // slot in 72-stride vectors

    // ---- staging (the ONLY __syncthreads) ----
    for (int idx = tid; idx < 10800; idx += TPB) {
        const int R = idx / 60, c = idx - R * 60;
        const int cc = c + (c >= 30 ? 6 : 0);
        sm[S_WHH + R * 72 + cc] = Whh[idx];
        sm[S_WIH + R * 72 + cc] = Wih[idx];
    }
    for (int idx = tid; idx < 4800; idx += TPB) {
        const int kk = idx / 80, c = idx - kk * 80;
        const int cc = (c < 30) ? c : ((c < 60) ? c + 6 : c + 8);
        sm[S_WF + kk * 88 + cc] = Wp[idx];
    }
    for (int idx = tid; idx < 180; idx += TPB) sm[S_BIH + idx] = bih[idx];
    for (int idx = tid; idx < 60;  idx += TPB) sm[S_BF + idx]  = bp[idx];
    for (int idx = tid; idx < GPB * Nn; idx += TPB)
        sm[S_HAS + idx] = has[(size_t)(b0 + (idx >> 5)) * Nn + (idx & 31)];
    __syncthreads();

    const float bhh0 = act ? bhh[d]        : 0.0f;
    const float bhh1 = act ? bhh[60 + d]   : 0.0f;
    const float bhh2 = act ? bhh[120 + d]  : 0.0f;
    const float bih0 = act ? sm[S_BIH + d]        : 0.0f;
    const float bih1 = act ? sm[S_BIH + 60 + d]   : 0.0f;
    const float bih2 = act ? sm[S_BIH + 120 + d]  : 0.0f;

    const float* w0p  = sm + S_WHH + d * 72 + khalf * 36;
    const float* wi0p = sm + S_WIH + d * 72 + khalf * 36;
    float* sHq = sm + S_H + quad * 576;    // [buf 2][sample 4][72]
    float* sPq = sm + S_PART + quad * 720; // [dim 60][12]

    int rp = 0;
    float h_old[4];
    float gi0[4], gi1[4], gi2[4], gn0[4], gn1[4], gn2[4];
    float p0[4], p1[4], p2[4];

    // ================== node scan ==================
    for (int ii = 0; ii < Nn; ii++) {
        const int i = dir ? (Nn - 1 - ii) : ii;

        // stage this node's z/dz (quad threads; bar before proj guaranteed below)
        {
            const int idx = w2 * 32 + lane;
            if (idx < 80) {
                const int m = idx / 20, c = idx % 20;
                const size_t base = ((size_t)(b0 + sb + m) * Nn + i) * SE;
                sm[S_ZD + (sb + m) * 20 + c] = (c < SE) ? z[base + c] : dz[base + c - SE];
            }
        }

        const int  cnt = dir ? g_bcnt[i] : g_fcnt[i];
        const int* lst = dir ? g_blist[i] : g_flist[i];

        #pragma unroll
        for (int m = 0; m < 4; m++) h_old[m] = 0.0f;

        if (cnt == 0) {
            if (khalf == 0 && act) {
                #pragma unroll
                for (int m = 0; m < 4; m++) sHq[rp * 288 + m * 72 + dsl] = 0.0f;
            }
            QUADBAR(barid);
        } else {
            if (khalf == 0 && act) {   // e=0 gi (same-lane rows, written earlier)
                const float* gb = gic + ((size_t)lst[0] * Bsz + b0 + sb) * 180;
                #pragma unroll
                for (int m = 0; m < 4; m++) {
                    gi0[m] = gb[m * 180 + d];
                    gi1[m] = gb[m * 180 + 60 + d];
                    gi2[m] = gb[m * 180 + 120 + d];
                }
            }
            for (int e = 0; e < cnt; e++) {
                const int j = lst[e];
                if (act && e > 0)
                    gemv_half(w0p, sHq + rp * 288 + khalf * 36, p0, p1, p2);
                if (khalf == 1 && act && e > 0) {
                    *(float4*)(sPq + d * 12 + 0) = make_float4(p0[0], p0[1], p0[2], p0[3]);
                    *(float4*)(sPq + d * 12 + 4) = make_float4(p1[0], p1[1], p1[2], p1[3]);
                    *(float4*)(sPq + d * 12 + 8) = make_float4(p2[0], p2[1], p2[2], p2[3]);
                }
                if (khalf == 0 && act && e + 1 < cnt) {   // prefetch next gi
                    const float* gb = gic + ((size_t)lst[e + 1] * Bsz + b0 + sb) * 180;
                    #pragma unroll
                    for (int m = 0; m < 4; m++) {
                        gn0[m] = gb[m * 180 + d];
                        gn1[m] = gb[m * 180 + 60 + d];
                        gn2[m] = gb[m * 180 + 120 + d];
                    }
                }
                if (e > 0) QUADBAR(barid);
                if (khalf == 0 && act) {
                    float q0[4] = {0,0,0,0}, q1[4] = {0,0,0,0}, q2[4] = {0,0,0,0};
                    if (e > 0) {
                        const float4 a = *(const float4*)(sPq + d * 12 + 0);
                        const float4 b = *(const float4*)(sPq + d * 12 + 4);
                        const float4 c = *(const float4*)(sPq + d * 12 + 8);
                        q0[0]=a.x; q0[1]=a.y; q0[2]=a.z; q0[3]=a.w;
                        q1[0]=b.x; q1[1]=b.y; q1[2]=b.z; q1[3]=b.w;
                        q2[0]=c.x; q2[1]=c.y; q2[2]=c.z; q2[3]=c.w;
                    } else {
                        #pragma unroll
                        for (int m = 0; m < 4; m++) { p0[m]=0; p1[m]=0; p2[m]=0; }
                    }
                    #pragma unroll
                    for (int m = 0; m < 4; m++) {
                        const float mask = sm[S_HAS + (sb + m) * 32 + j];
                        const float r  = sigmf_(p0[m] + q0[m] + gi0[m] + bhh0);
                        const float u  = sigmf_(p1[m] + q1[m] + gi1[m] + bhh1);
                        const float nv = tanhsafe_(gi2[m] + r * (p2[m] + q2[m] + bhh2));
                        const float ho = h_old[m];
                        const float h2 = (1.0f - u) * nv + u * ho;
                        const float hn = ho + mask * (h2 - ho);
                        h_old[m] = hn;
                        sHq[(1 - rp) * 288 + m * 72 + dsl] = hn;
                    }
                    if (e + 1 < cnt) {
                        #pragma unroll
                        for (int m = 0; m < 4; m++) {
                            gi0[m]=gn0[m]; gi1[m]=gn1[m]; gi2[m]=gn2[m];
                        }
                    }
                }
                QUADBAR(barid);
                rp ^= 1;
            }
        }

        // ---- projection (K split: khalf0 h[0:30); khalf1 h[30:60) + zd) ----
        float pp[4];
        if (act) {
            unsigned long long A[4] = {0,0,0,0};
            const float* wf = sm + S_WF + d * 88 + khalf * 36;
            const float* hb = sHq + rp * 288 + khalf * 36;
            #pragma unroll
            for (int qq = 0; qq < 7; qq++) {
                const ulonglong2 w = *(const ulonglong2*)(wf + 4 * qq);
                #pragma unroll
                for (int m = 0; m < 4; m++) {
                    const ulonglong2 h = *(const ulonglong2*)(hb + m * 72 + 4 * qq);
                    fma2(A[m], w.x, h.x); fma2(A[m], w.y, h.y);
                }
            }
            {
                const unsigned long long wt = *(const unsigned long long*)(wf + 28);
                #pragma unroll
                for (int m = 0; m < 4; m++) {
                    const unsigned long long ht = *(const unsigned long long*)(hb + m * 72 + 28);
                    fma2(A[m], wt, ht);
                }
            }
            if (khalf == 1) {   // zd part: Wf row @ +68, zd 20 floats per sample
                const float* wz = sm + S_WF + d * 88 + 68;
                #pragma unroll
                for (int qq = 0; qq < 5; qq++) {
                    const ulonglong2 w = *(const ulonglong2*)(wz + 4 * qq);
                    #pragma unroll
                    for (int m = 0; m < 4; m++) {
                        const ulonglong2 x =
                            *(const ulonglong2*)(sm + S_ZD + (sb + m) * 20 + 4 * qq);
                        fma2(A[m], w.x, x.x); fma2(A[m], w.y, x.y);
                    }
                }
            }
            #pragma unroll
            for (int m = 0; m < 4; m++) pp[m] = red2(A[m]);
        }
        if (khalf == 1 && act)
            *(float4*)(sPq + d * 12) = make_float4(pp[0], pp[1], pp[2], pp[3]);
        QUADBAR(barid);
        if (khalf == 0 && act) {
            const float4 q = *(const float4*)(sPq + d * 12);
            const float qa[4] = {q.x, q.y, q.z, q.w};
            const float bf = sm[S_BF + d];
            #pragma unroll
            for (int m = 0; m < 4; m++) {
                float val = pp[m] + qa[m] + bf;
                if (dir == 0) val = tanhsafe_(val);
                sm[S_RHO + (sb + m) * 72 + dsl] = val;
                grho[((size_t)i * Bsz + b0 + sb + m) * 60 + d] = val;
            }
        }
        QUADBAR(barid);   // rho complete (both halves, all dims)

        // ---- gi for node i (K split over rho) ----
        if (act)
            gemv_half(wi0p, sm + S_RHO + sb * 72 + khalf * 36, p0, p1, p2);
        if (khalf == 1 && act) {
            *(float4*)(sPq + d * 12 + 0) = make_float4(p0[0], p0[1], p0[2], p0[3]);
            *(float4*)(sPq + d * 12 + 4) = make_float4(p1[0], p1[1], p1[2], p1[3]);
            *(float4*)(sPq + d * 12 + 8) = make_float4(p2[0], p2[1], p2[2], p2[3]);
        }
        QUADBAR(barid);
        if (khalf == 0 && act) {
            const float4 a = *(const float4*)(sPq + d * 12 + 0);
            const float4 b = *(const float4*)(sPq + d * 12 + 4);
            const float4 c = *(const float4*)(sPq + d * 12 + 8);
            const float qa[4] = {a.x, a.y, a.z, a.w};
            const float qb[4] = {b.x, b.y, b.z, b.w};
            const float qc[4] = {c.x, c.y, c.z, c.w};
            #pragma unroll
            for (int m = 0; m < 4; m++) {
                float* gp = gic + ((size_t)i * Bsz + b0 + sb + m) * 180;
                gp[d]       = p0[m] + qa[m] + bih0;
                gp[60 + d]  = p1[m] + qb[m] + bih1;
                gp[120 + d] = p2[m] + qc[m] + bih2;
            }
        }
        QUADBAR(barid);   // PART/RHO free for next node
    }

    // ================== alpha scan ==================
    #pragma unroll
    for (int m = 0; m < 4; m++) h_old[m] = 0.0f;
    const int steps = dir ? IIN : OOUT;
    for (int s = 0; s < steps; s++) {
        const int i = dir ? (IIN - 1 - s) : (Nn - OOUT + s);
        if (khalf == 0 && act) {
            const float* gb = gic + ((size_t)i * Bsz + b0 + sb) * 180;
            #pragma unroll
            for (int m = 0; m < 4; m++) {
                gi0[m] = gb[m * 180 + d];
                gi1[m] = gb[m * 180 + 60 + d];
                gi2[m] = gb[m * 180 + 120 + d];
            }
        }
        if (act && s > 0)
            gemv_half(w0p, sHq + rp * 288 + khalf * 36, p0, p1, p2);
        if (khalf == 1 && act && s > 0) {
            *(float4*)(sPq + d * 12 + 0) = make_float4(p0[0], p0[1], p0[2], p0[3]);
            *(float4*)(sPq + d * 12 + 4) = make_float4(p1[0], p1[1], p1[2], p1[3]);
            *(float4*)(sPq + d * 12 + 8) = make_float4(p2[0], p2[1], p2[2], p2[3]);
        }
        if (s > 0) QUADBAR(barid);
        if (khalf == 0 && act) {
            float q0[4] = {0,0,0,0}, q1[4] = {0,0,0,0}, q2[4] = {0,0,0,0};
            if (s > 0) {
                const float4 a = *(const float4*)(sPq + d * 12 + 0);
                const float4 b = *(const float4*)(sPq + d * 12 + 4);
                const float4 c = *(const float4*)(sPq + d * 12 + 8);
                q0[0]=a.x; q0[1]=a.y; q0[2]=a.z; q0[3]=a.w;
                q1[0]=b.x; q1[1]=b.y; q1[2]=b.z; q1[3]=b.w;
                q2[0]=c.x; q2[1]=c.y; q2[2]=c.z; q2[3]=c.w;
            } else {
                #pragma unroll
                for (int m = 0; m < 4; m++) { p0[m]=0; p1[m]=0; p2[m]=0; }
            }
            #pragma unroll
            for (int m = 0; m < 4; m++) {
                const float mask = sm[S_HAS + (sb + m) * 32 + i];
                const float r  = sigmf_(p0[m] + q0[m] + gi0[m] + bhh0);
                const float u  = sigmf_(p1[m] + q1[m] + gi1[m] + bhh1);
                const float nv = tanhsafe_(gi2[m] + r * (p2[m] + q2[m] + bhh2));
                const float ho = h_old[m];
                const float h2 = (1.0f - u) * nv + u * ho;
                const float hn = ho + mask * (h2 - ho);
                h_old[m] = hn;
                sHq[(1 - rp) * 288 + m * 72 + dsl] = hn;
            }
        }
        QUADBAR(barid);
        rp ^= 1;
    }
    if (khalf == 0 && act) {
        float* ga = dir ? g_ab : g_af;
        #pragma unroll
        for (int m = 0; m < 4; m++)
            ga[(size_t)(b0 + sb + m) * 60 + d] = h_old[m];
    }
}

// ============================================================
// Heads: blocks [0,128) role_prob; [128,144) instr_prob + value
// out: [0,5120) instr | [5120,234496) roles | [234496,235520) value
// ============================================================
__global__ void k_heads(const float* __restrict__ has,
                        const float* __restrict__ Wu, const float* __restrict__ bu,
                        const float* __restrict__ Wa, const float* __restrict__ ba,
                        const float* __restrict__ Wc, const float* __restrict__ bc,
                        float* __restrict__ out)
{
    const int tid = threadIdx.x;
    if (blockIdx.x < 128) {
        __shared__ __align__(16) float sWu[7 * 120];
        __shared__ float sbu[7];
        for (int idx = tid; idx < 840; idx += blockDim.x) sWu[idx] = Wu[idx];
        if (tid < 7) sbu[tid] = bu[tid];
        __syncthreads();

        const int t = blockIdx.x * 256 + tid;
        const int b = t >> 5;
        const int n = t & 31;

        float acc[7];
        #pragma unroll
        for (int r = 0; r < 7; r++) acc[r] = sbu[r];

        const float4* rf = (const float4*)(g_rho_f + ((size_t)n * Bsz + b) * 60);
        const float4* rb = (const float4*)(g_rho_b + ((size_t)n * Bsz + b) * 60);
        #pragma unroll
        for (int q = 0; q < 15; q++) {
            const float4 f = rf[q];
            #pragma unroll
            for (int r = 0; r < 7; r++) {
                const float4 w = *(const float4*)(sWu + r * 120 + q * 4);
                acc[r] += w.x*f.x + w.y*f.y + w.z*f.z + w.w*f.w;
            }
        }
        #pragma unroll
        for (int q = 0; q < 15; q++) {
            const float4 f = rb[q];
            #pragma unroll
            for (int r = 0; r < 7; r++) {
                const float4 w = *(const float4*)(sWu + r * 120 + 60 + q * 4);
                acc[r] += w.x*f.x + w.y*f.y + w.z*f.z + w.w*f.w;
            }
        }
        const float m = has[b * Nn + n];
        float l[7], mx = -1e30f;
        #pragma unroll
        for (int r = 0; r < 7; r++) { l[r] = (m != 0.0f) ? acc[r] : -60.0f; mx = fmaxf(mx, l[r]); }
        float s = 0.0f;
        #pragma unroll
        for (int r = 0; r < 7; r++) { l[r] = __expf(l[r] - mx); s += l[r]; }
        const float inv = __fdividef(1.0f, s);
        float* ro = out + 5120;
        #pragma unroll
        for (int r = 0; r < 7; r++) ro[((size_t)b * 7 + r) * 32 + n] = l[r] * inv;
    } else {
        __shared__ __align__(16) float sWa[5 * 120];
        __shared__ __align__(16) float sWc[120];
        __shared__ float sba[5];
        __shared__ float sbc;
        for (int idx = tid; idx < 600; idx += blockDim.x) sWa[idx] = Wa[idx];
        for (int idx = tid; idx < 120; idx += blockDim.x) sWc[idx] = Wc[idx];
        if (tid < 5) sba[tid] = ba[tid];
        if (tid == 0) sbc = bc[0];
        __syncthreads();

        const int t    = (blockIdx.x - 128) * 256 + tid;
        const int b    = t >> 2;
        const int lane = t & 3;

        float acc[6];
        #pragma unroll
        for (int a = 0; a < 6; a++) acc[a] = 0.0f;

        const float4* af = (const float4*)(g_af + (size_t)b * 60);
        const float4* ab = (const float4*)(g_ab + (size_t)b * 60);
        for (int q = lane; q < 30; q += 4) {
            const float4 f = (q < 15) ? af[q] : ab[q - 15];
            #pragma unroll
            for (int a = 0; a < 5; a++) {
                const float4 w = *(const float4*)(sWa + a * 120 + q * 4);
                acc[a] += w.x*f.x + w.y*f.y + w.z*f.z + w.w*f.w;
            }
            const float4 wc = *(const float4*)(sWc + q * 4);
            acc[5] += wc.x*f.x + wc.y*f.y + wc.z*f.z + wc.w*f.w;
        }
        #pragma unroll
        for (int off = 1; off < 4; off <<= 1) {
            #pragma unroll
            for (int a = 0; a < 6; a++)
                acc[a] += __shfl_xor_sync(0xffffffffu, acc[a], off);
        }
        if (lane == 0) {
            float l[5], mx = -1e30f;
            #pragma unroll
            for (int a = 0; a < 5; a++) { l[a] = acc[a] + sba[a]; mx = fmaxf(mx, l[a]); }
            float s = 0.0f;
            #pragma unroll
            for (int a = 0; a < 5; a++) { l[a] = __expf(l[a] - mx); s += l[a]; }
            const float inv = __fdividef(1.0f, s);
            #pragma unroll
            for (int a = 0; a < 5; a++) out[b * 5 + a] = l[a] * inv;
            out[5120 + Bsz * 7 * Nn + b] = acc[5] + sbc;   // value @ 234496
        }
    }
}

// ============================================================
extern "C" void kernel_launch(void* const* d_in, const int* in_sizes, int n_in,
                              void* d_out, int out_size)
{
    const float* has   = (const float*)d_in[0];
    const float* z     = (const float*)d_in[1];
    const float* dz    = (const float*)d_in[2];
    const unsigned char* adj = (const unsigned char*)d_in[3];
    const float* Wih_f = (const float*)d_in[4];
    const float* Whh_f = (const float*)d_in[5];
    const float* bih_f = (const float*)d_in[6];
    const float* bhh_f = (const float*)d_in[7];
    const float* Wih_b = (const float*)d_in[8];
    const float* Whh_b = (const float*)d_in[9];
    const float* bih_b = (const float*)d_in[10];
    const float* bhh_b = (const float*)d_in[11];
    const float* Wf    = (const float*)d_in[12];
    const float* bf    = (const float*)d_in[13];
    const float* Wb    = (const float*)d_in[14];
    const float* bb    = (const float*)d_in[15];
    const float* Wa    = (const float*)d_in[16];
    const float* ba    = (const float*)d_in[17];
    const float* Wc    = (const float*)d_in[18];
    const float* bc    = (const float*)d_in[19];
    const float* Wu    = (const float*)d_in[20];
    const float* bu    = (const float*)d_in[21];
    float* out = (float*)d_out;

    const size_t smem = SMEM_FLOATS * sizeof(float);   // ~154 KB -> 1 block/SM
    cudaFuncSetAttribute(k_scan, cudaFuncAttributeMaxDynamicSharedMemorySize, (int)smem);

    k_prep<<<1, 256>>>(adj);
    k_scan<<<128, TPB, smem>>>(has, z, dz,
                               Wih_f, Whh_f, bih_f, bhh_f,
                               Wih_b, Whh_b, bih_b, bhh_b,
                               Wf, bf, Wb, bb);
    k_heads<<<144, 256>>>(has, Wu, bu, Wa, ba, Wc, bc, out);
}

// round 13
// speedup vs baseline: 1.4695x; 1.4695x over previous
#include <cuda_runtime.h>
#include <math.h>

#define Bsz   1024
#define Nn    32
#define SE    10
#define OOUT  5
#define IIN   6
#define GPB   16     // samples per block
#define TPB   256    // 8 warps = 4 pairs; pair owns 4 samples; warp owns 30 dims

// ---- shared memory layout (float offsets; all 16B-aligned) ----
#define S_WHH 0        // 180 x 68 = 12240  (first reused as adj scratch)
#define S_WIH 12240    // 12240
#define S_WF  24480    // 60 x 84 = 5040
#define S_BIH 29520    // 180
#define S_BF  29700    // 60
#define S_HAS 29760    // 16*32 = 512
#define S_ZD  30272    // 16*20 = 320
#define S_H   30592    // 4 pairs x 2 bufs x 4 samples x 64 = 2048
#define S_RHO 32640    // 16*64 = 1024
#define S_CNT 33664    // 32 ints
#define S_LST 33696    // 32*32 ints
#define SMEM_FLOATS 34720   // ~139 KB -> 1 block/SM

// ---- device scratch ----
__device__ float g_rho_f[Nn * Bsz * 60];
__device__ float g_rho_b[Nn * Bsz * 60];
__device__ float g_af[Bsz * 60];
__device__ float g_ab[Bsz * 60];
__device__ float g_gi_f[Nn * Bsz * 180];   // gi cache incl. bih: [node][b][row]
__device__ float g_gi_b[Nn * Bsz * 180];

__device__ __forceinline__ void fma2(unsigned long long& a,
                                     unsigned long long b, unsigned long long c) {
    asm("fma.rn.f32x2 %0,%1,%2,%0;" : "+l"(a) : "l"(b), "l"(c));
}
__device__ __forceinline__ float red2(unsigned long long v) {
    float x, y;
    asm("mov.b64 {%0,%1},%2;" : "=f"(x), "=f"(y) : "l"(v));
    return x + y;
}
__device__ __forceinline__ unsigned long long seed2(float x) {
    return (unsigned long long)__float_as_uint(x);   // (x, +0.0f)
}
__device__ __forceinline__ float sigmf_(float x) {
    return __fdividef(1.0f, 1.0f + __expf(-x));
}
__device__ __forceinline__ float tanhsafe_(float x) {
    float a = fabsf(x);
    float e = __expf(-2.0f * a);
    float t = __fdividef(1.0f - e, 1.0f + e);
    return copysignf(t, x);
}
#define PAIRBAR(id) asm volatile("bar.sync %0, %1;" :: "r"(id), "r"(64) : "memory")

// ============================================================
// Main scan: 128 blocks (64 fwd, 64 bwd), 16 samples each.
// Warp-PAIR owns 4 samples; warp owns 30 dims (lane = 1 dim, 3 gate rows).
// Prep (adj decode + edge lists) fused at block start.
// One 64-thread named barrier per GRU step; no node-end barrier.
// ============================================================
__global__ void __launch_bounds__(TPB) k_scan(
    const unsigned char* __restrict__ adj_raw,
    const float* __restrict__ has, const float* __restrict__ z, const float* __restrict__ dz,
    const float* __restrict__ Wih_f, const float* __restrict__ Whh_f,
    const float* __restrict__ bih_f, const float* __restrict__ bhh_f,
    const float* __restrict__ Wih_b, const float* __restrict__ Whh_b,
    const float* __restrict__ bih_b, const float* __restrict__ bhh_b,
    const float* __restrict__ Wfp, const float* __restrict__ bfp,
    const float* __restrict__ Wbp, const float* __restrict__ bbp)
{
    extern __shared__ __align__(16) float sm[];
    int* smi = (int*)sm;
    const int dir = blockIdx.x >> 6;
    const int b0  = (blockIdx.x & 63) * GPB;
    const float* Wih = dir ? Wih_b : Wih_f;
    const float* Whh = dir ? Whh_b : Whh_f;
    const float* bih = dir ? bih_b : bih_f;
    const float* bhh = dir ? bhh_b : bhh_f;
    const float* Wp  = dir ? Wbp   : Wfp;
    const float* bp  = dir ? bbp   : bfp;
    float* grho = dir ? g_rho_b : g_rho_f;
    float* gic  = dir ? g_gi_b  : g_gi_f;

    const int  tid   = threadIdx.x;
    const int  warp  = tid >> 5;
    const int  lane  = tid & 31;
    const int  pair  = warp >> 1;        // 0..3
    const int  half  = warp & 1;         // 0: dims 0-29, 1: dims 30-59
    const int  sb    = pair * 4;         // pair's sample base
    const int  lpair = half * 32 + lane; // 0..63 within pair
    const int  barid = 1 + pair;
    const bool act   = lane < 30;
    const int  d     = half * 30 + lane; // owned dim (if act)

    // ---- fused prep: decode adj (dtype-ambiguous) + edge lists for this dir
    if (tid < 2) smi[1024 + tid] = 0;
    __syncthreads();
    {
        int f_gt1 = 0, f_off4 = 0;
        for (int t = tid; t < Nn * Nn; t += TPB) {
            unsigned char c = adj_raw[t];
            if (c > 1) f_gt1 = 1;
            if (c == 1 && (t & 3) != 0) f_off4 = 1;
        }
        if (f_gt1)  atomicOr(&smi[1024], 1);
        if (f_off4) atomicOr(&smi[1025], 1);
    }
    __syncthreads();
    {
        const int mode = smi[1024] ? 1 : (smi[1025] ? 0 : 2);
        for (int e = tid; e < Nn * Nn; e += TPB) {
            float v;
            if (mode == 1)      v = ((const float*)adj_raw)[e];
            else if (mode == 2) v = (float)(((const int*)adj_raw)[e]);
            else                v = (float)adj_raw[e];
            sm[e] = v;
        }
    }
    __syncthreads();
    if (tid < Nn) {
        const int i = tid; int c = 0;
        if (dir == 0) {   // fwd: edges adj[j][i]!=0, j ascending
            for (int j = 0; j < Nn; j++)
                if (sm[j * Nn + i] != 0.0f) smi[S_LST + i * 32 + (c++)] = j;
        } else {          // bwd: edges adj[i][j]!=0, j descending
            for (int j = Nn - 1; j >= 0; j--)
                if (sm[i * Nn + j] != 0.0f) smi[S_LST + i * 32 + (c++)] = j;
        }
        smi[S_CNT + i] = c;
    }
    __syncthreads();

    // ---- block-wide weight/bias staging (overwrites adj scratch)
    for (int idx = tid; idx < 10800; idx += TPB) {
        const int r = idx / 60, c = idx - r * 60;
        sm[S_WHH + r * 68 + c] = Whh[idx];
        sm[S_WIH + r * 68 + c] = Wih[idx];
    }
    for (int idx = tid; idx < 4800; idx += TPB)
        sm[S_WF + (idx / 80) * 84 + (idx % 80)] = Wp[idx];
    for (int idx = tid; idx < 180; idx += TPB) sm[S_BIH + idx] = bih[idx];
    for (int idx = tid; idx < 60;  idx += TPB) sm[S_BF + idx]  = bp[idx];
    for (int idx = tid; idx < GPB * Nn; idx += TPB)
        sm[S_HAS + idx] = has[(size_t)(b0 + (idx >> 5)) * Nn + (idx & 31)];
    __syncthreads();

    const float bhh0 = act ? bhh[d]        : 0.0f;
    const float bhh1 = act ? bhh[60 + d]   : 0.0f;
    const float bhh2 = act ? bhh[120 + d]  : 0.0f;
    const float bih0 = act ? sm[S_BIH + d]        : 0.0f;
    const float bih1 = act ? sm[S_BIH + 60 + d]   : 0.0f;
    const float bih2 = act ? sm[S_BIH + 120 + d]  : 0.0f;

    float* sHp = sm + S_H + pair * 512;   // [buf 2][sample 4][64]
    const float* w0p = sm + S_WHH + d * 68;
    const float* w1p = sm + S_WHH + (60 + d) * 68;
    const float* w2p = sm + S_WHH + (120 + d) * 68;

    int rp = 0;
    float h_old[4];
    float gi0[4], gi1[4], gi2[4], gn0[4], gn1[4], gn2[4];
    float a0[4], a1[4], a2[4];

    // ================== node scan ==================
    for (int ii = 0; ii < Nn; ii++) {
        const int i = dir ? (Nn - 1 - ii) : ii;

        // stage this node's z/dz for the pair's samples
        for (int idx = lpair; idx < 80; idx += 64) {
            const int m = idx / 20, c = idx % 20;
            const size_t base = ((size_t)(b0 + sb + m) * Nn + i) * SE;
            sm[S_ZD + (sb + m) * 20 + c] = (c < SE) ? z[base + c] : dz[base + c - SE];
        }

        const int  cnt = smi[S_CNT + i];
        const int* lst = smi + S_LST + i * 32;

        #pragma unroll
        for (int m = 0; m < 4; m++) h_old[m] = 0.0f;

        if (cnt == 0) {
            if (act) {
                #pragma unroll
                for (int m = 0; m < 4; m++) sHp[rp * 256 + m * 64 + d] = 0.0f;
            }
            PAIRBAR(barid);
        } else {
            if (act) {   // e=0 gi (rows written by this same lane earlier)
                const float* gb = gic + ((size_t)lst[0] * Bsz + b0 + sb) * 180;
                #pragma unroll
                for (int m = 0; m < 4; m++) {
                    gi0[m] = gb[m * 180 + d];
                    gi1[m] = gb[m * 180 + 60 + d];
                    gi2[m] = gb[m * 180 + 120 + d];
                }
            }
            for (int e = 0; e < cnt; e++) {
                const int j = lst[e];
                if (act) {
                    if (e > 0) {
                        unsigned long long A0[4], A1[4], A2[4];
                        #pragma unroll
                        for (int m = 0; m < 4; m++) { A0[m]=0; A1[m]=0; A2[m]=0; }
                        const float* Hb = sHp + rp * 256;
                        #pragma unroll
                        for (int q = 0; q < 15; q++) {
                            const ulonglong2 w0 = *(const ulonglong2*)(w0p + q * 4);
                            const ulonglong2 w1 = *(const ulonglong2*)(w1p + q * 4);
                            const ulonglong2 w2 = *(const ulonglong2*)(w2p + q * 4);
                            #pragma unroll
                            for (int m = 0; m < 4; m++) {
                                const ulonglong2 h = *(const ulonglong2*)(Hb + m * 64 + q * 4);
                                fma2(A0[m], w0.x, h.x); fma2(A0[m], w0.y, h.y);
                                fma2(A1[m], w1.x, h.x); fma2(A1[m], w1.y, h.y);
                                fma2(A2[m], w2.x, h.x); fma2(A2[m], w2.y, h.y);
                            }
                        }
                        #pragma unroll
                        for (int m = 0; m < 4; m++) {
                            a0[m] = red2(A0[m]); a1[m] = red2(A1[m]); a2[m] = red2(A2[m]);
                        }
                    } else {
                        #pragma unroll
                        for (int m = 0; m < 4; m++) { a0[m]=0; a1[m]=0; a2[m]=0; }
                    }
                    if (e + 1 < cnt) {   // prefetch next gi
                        const float* gb = gic + ((size_t)lst[e + 1] * Bsz + b0 + sb) * 180;
                        #pragma unroll
                        for (int m = 0; m < 4; m++) {
                            gn0[m] = gb[m * 180 + d];
                            gn1[m] = gb[m * 180 + 60 + d];
                            gn2[m] = gb[m * 180 + 120 + d];
                        }
                    }
                    #pragma unroll
                    for (int m = 0; m < 4; m++) {
                        const float mask = sm[S_HAS + (sb + m) * 32 + j];
                        const float r  = sigmf_(a0[m] + gi0[m] + bhh0);
                        const float u  = sigmf_(a1[m] + gi1[m] + bhh1);
                        const float nv = tanhsafe_(gi2[m] + r * (a2[m] + bhh2));
                        const float ho = h_old[m];
                        const float h2 = (1.0f - u) * nv + u * ho;
                        const float hn = ho + mask * (h2 - ho);
                        h_old[m] = hn;
                        sHp[(1 - rp) * 256 + m * 64 + d] = hn;
                    }
                    if (e + 1 < cnt) {
                        #pragma unroll
                        for (int m = 0; m < 4; m++) {
                            gi0[m]=gn0[m]; gi1[m]=gn1[m]; gi2[m]=gn2[m];
                        }
                    }
                }
                PAIRBAR(barid);
                rp ^= 1;
            }
        }

        // ---- projection: lane -> dim d, 4 samples (h complete after bar)
        if (act) {
            const ulonglong2* Wr = (const ulonglong2*)(sm + S_WF + d * 84);
            #pragma unroll
            for (int m = 0; m < 4; m++) {
                unsigned long long acc = seed2(sm[S_BF + d]);
                const ulonglong2* Hh = (const ulonglong2*)(sHp + rp * 256 + m * 64);
                #pragma unroll
                for (int q = 0; q < 15; q++) {
                    const ulonglong2 w = Wr[q], h = Hh[q];
                    fma2(acc, w.x, h.x); fma2(acc, w.y, h.y);
                }
                const ulonglong2* Zd = (const ulonglong2*)(sm + S_ZD + (sb + m) * 20);
                #pragma unroll
                for (int q = 0; q < 5; q++) {
                    const ulonglong2 w = Wr[15 + q], x = Zd[q];
                    fma2(acc, w.x, x.x); fma2(acc, w.y, x.y);
                }
                float val = red2(acc);
                if (dir == 0) val = tanhsafe_(val);
                sm[S_RHO + (sb + m) * 64 + d] = val;
                grho[((size_t)i * Bsz + b0 + sb + m) * 60 + d] = val;
            }
        }
        PAIRBAR(barid);   // rho complete (both halves)

        // ---- gi for node i: rows {d, 60+d, 120+d} x 4 samples (Wih in smem).
        // No node-end barrier: next node's first in-loop PAIRBAR orders the
        // partner's sRHO reads here against the next projection's overwrites.
        if (act) {
            unsigned long long A0[4], A1[4], A2[4];
            #pragma unroll
            for (int m = 0; m < 4; m++) {
                A0[m] = seed2(bih0); A1[m] = seed2(bih1); A2[m] = seed2(bih2);
            }
            const float* u0p = sm + S_WIH + d * 68;
            const float* u1p = sm + S_WIH + (60 + d) * 68;
            const float* u2p = sm + S_WIH + (120 + d) * 68;
            const float* Rb = sm + S_RHO + sb * 64;
            #pragma unroll
            for (int q = 0; q < 15; q++) {
                const ulonglong2 w0 = *(const ulonglong2*)(u0p + q * 4);
                const ulonglong2 w1 = *(const ulonglong2*)(u1p + q * 4);
                const ulonglong2 w2 = *(const ulonglong2*)(u2p + q * 4);
                #pragma unroll
                for (int m = 0; m < 4; m++) {
                    const ulonglong2 rv = *(const ulonglong2*)(Rb + m * 64 + q * 4);
                    fma2(A0[m], w0.x, rv.x); fma2(A0[m], w0.y, rv.y);
                    fma2(A1[m], w1.x, rv.x); fma2(A1[m], w1.y, rv.y);
                    fma2(A2[m], w2.x, rv.x); fma2(A2[m], w2.y, rv.y);
                }
            }
            #pragma unroll
            for (int m = 0; m < 4; m++) {
                float* gp = gic + ((size_t)i * Bsz + b0 + sb + m) * 180;
                gp[d]       = red2(A0[m]);
                gp[60 + d]  = red2(A1[m]);
                gp[120 + d] = red2(A2[m]);
            }
        }
    }

    // ================== alpha scan ==================
    #pragma unroll
    for (int m = 0; m < 4; m++) h_old[m] = 0.0f;
    const int steps = dir ? IIN : OOUT;
    for (int s = 0; s < steps; s++) {
        const int i = dir ? (IIN - 1 - s) : (Nn - OOUT + s);
        if (act) {
            const float* gb = gic + ((size_t)i * Bsz + b0 + sb) * 180;
            #pragma unroll
            for (int m = 0; m < 4; m++) {
                gi0[m] = gb[m * 180 + d];
                gi1[m] = gb[m * 180 + 60 + d];
                gi2[m] = gb[m * 180 + 120 + d];
            }
            if (s > 0) {
                unsigned long long A0[4], A1[4], A2[4];
                #pragma unroll
                for (int m = 0; m < 4; m++) { A0[m]=0; A1[m]=0; A2[m]=0; }
                const float* Hb = sHp + rp * 256;
                #pragma unroll
                for (int q = 0; q < 15; q++) {
                    const ulonglong2 w0 = *(const ulonglong2*)(w0p + q * 4);
                    const ulonglong2 w1 = *(const ulonglong2*)(w1p + q * 4);
                    const ulonglong2 w2 = *(const ulonglong2*)(w2p + q * 4);
                    #pragma unroll
                    for (int m = 0; m < 4; m++) {
                        const ulonglong2 h = *(const ulonglong2*)(Hb + m * 64 + q * 4);
                        fma2(A0[m], w0.x, h.x); fma2(A0[m], w0.y, h.y);
                        fma2(A1[m], w1.x, h.x); fma2(A1[m], w1.y, h.y);
                        fma2(A2[m], w2.x, h.x); fma2(A2[m], w2.y, h.y);
                    }
                }
                #pragma unroll
                for (int m = 0; m < 4; m++) {
                    a0[m] = red2(A0[m]); a1[m] = red2(A1[m]); a2[m] = red2(A2[m]);
                }
            } else {
                #pragma unroll
                for (int m = 0; m < 4; m++) { a0[m]=0; a1[m]=0; a2[m]=0; }
            }
            #pragma unroll
            for (int m = 0; m < 4; m++) {
                const float mask = sm[S_HAS + (sb + m) * 32 + i];
                const float r  = sigmf_(a0[m] + gi0[m] + bhh0);
                const float u  = sigmf_(a1[m] + gi1[m] + bhh1);
                const float nv = tanhsafe_(gi2[m] + r * (a2[m] + bhh2));
                const float ho = h_old[m];
                const float h2 = (1.0f - u) * nv + u * ho;
                const float hn = ho + mask * (h2 - ho);
                h_old[m] = hn;
                sHp[(1 - rp) * 256 + m * 64 + d] = hn;
            }
        }
        PAIRBAR(barid);
        rp ^= 1;
    }
    if (act) {
        float* ga = dir ? g_ab : g_af;
        #pragma unroll
        for (int m = 0; m < 4; m++)
            ga[(size_t)(b0 + sb + m) * 60 + d] = h_old[m];
    }
}

// ============================================================
// Heads: blocks [0,128) role_prob; [128,144) instr_prob + value
// out: [0,5120) instr | [5120,234496) roles | [234496,235520) value
// ============================================================
__global__ void k_heads(const float* __restrict__ has,
                        const float* __restrict__ Wu, const float* __restrict__ bu,
                        const float* __restrict__ Wa, const float* __restrict__ ba,
                        const float* __restrict__ Wc, const float* __restrict__ bc,
                        float* __restrict__ out)
{
    const int tid = threadIdx.x;
    if (blockIdx.x < 128) {
        __shared__ __align__(16) float sWu[7 * 120];
        __shared__ float sbu[7];
        for (int idx = tid; idx < 840; idx += blockDim.x) sWu[idx] = Wu[idx];
        if (tid < 7) sbu[tid] = bu[tid];
        __syncthreads();

        const int t = blockIdx.x * 256 + tid;
        const int b = t >> 5;
        const int n = t & 31;

        float acc[7];
        #pragma unroll
        for (int r = 0; r < 7; r++) acc[r] = sbu[r];

        const float4* rf = (const float4*)(g_rho_f + ((size_t)n * Bsz + b) * 60);
        const float4* rb = (const float4*)(g_rho_b + ((size_t)n * Bsz + b) * 60);
        #pragma unroll
        for (int q = 0; q < 15; q++) {
            const float4 f = rf[q];
            #pragma unroll
            for (int r = 0; r < 7; r++) {
                const float4 w = *(const float4*)(sWu + r * 120 + q * 4);
                acc[r] += w.x*f.x + w.y*f.y + w.z*f.z + w.w*f.w;
            }
        }
        #pragma unroll
        for (int q = 0; q < 15; q++) {
            const float4 f = rb[q];
            #pragma unroll
            for (int r = 0; r < 7; r++) {
                const float4 w = *(const float4*)(sWu + r * 120 + 60 + q * 4);
                acc[r] += w.x*f.x + w.y*f.y + w.z*f.z + w.w*f.w;
            }
        }
        const float m = has[b * Nn + n];
        float l[7], mx = -1e30f;
        #pragma unroll
        for (int r = 0; r < 7; r++) { l[r] = (m != 0.0f) ? acc[r] : -60.0f; mx = fmaxf(mx, l[r]); }
        float s = 0.0f;
        #pragma unroll
        for (int r = 0; r < 7; r++) { l[r] = __expf(l[r] - mx); s += l[r]; }
        const float inv = __fdividef(1.0f, s);
        float* ro = out + 5120;
        #pragma unroll
        for (int r = 0; r < 7; r++) ro[((size_t)b * 7 + r) * 32 + n] = l[r] * inv;
    } else {
        __shared__ __align__(16) float sWa[5 * 120];
        __shared__ __align__(16) float sWc[120];
        __shared__ float sba[5];
        __shared__ float sbc;
        for (int idx = tid; idx < 600; idx += blockDim.x) sWa[idx] = Wa[idx];
        for (int idx = tid; idx < 120; idx += blockDim.x) sWc[idx] = Wc[idx];
        if (tid < 5) sba[tid] = ba[tid];
        if (tid == 0) sbc = bc[0];
        __syncthreads();

        const int t    = (blockIdx.x - 128) * 256 + tid;
        const int b    = t >> 2;
        const int lane = t & 3;

        float acc[6];
        #pragma unroll
        for (int a = 0; a < 6; a++) acc[a] = 0.0f;

        const float4* af = (const float4*)(g_af + (size_t)b * 60);
        const float4* ab = (const float4*)(g_ab + (size_t)b * 60);
        for (int q = lane; q < 30; q += 4) {
            const float4 f = (q < 15) ? af[q] : ab[q - 15];
            #pragma unroll
            for (int a = 0; a < 5; a++) {
                const float4 w = *(const float4*)(sWa + a * 120 + q * 4);
                acc[a] += w.x*f.x + w.y*f.y + w.z*f.z + w.w*f.w;
            }
            const float4 wc = *(const float4*)(sWc + q * 4);
            acc[5] += wc.x*f.x + wc.y*f.y + wc.z*f.z + wc.w*f.w;
        }
        #pragma unroll
        for (int off = 1; off < 4; off <<= 1) {
            #pragma unroll
            for (int a = 0; a < 6; a++)
                acc[a] += __shfl_xor_sync(0xffffffffu, acc[a], off);
        }
        if (lane == 0) {
            float l[5], mx = -1e30f;
            #pragma unroll
            for (int a = 0; a < 5; a++) { l[a] = acc[a] + sba[a]; mx = fmaxf(mx, l[a]); }
            float s = 0.0f;
            #pragma unroll
            for (int a = 0; a < 5; a++) { l[a] = __expf(l[a] - mx); s += l[a]; }
            const float inv = __fdividef(1.0f, s);
            #pragma unroll
            for (int a = 0; a < 5; a++) out[b * 5 + a] = l[a] * inv;
            out[5120 + Bsz * 7 * Nn + b] = acc[5] + sbc;   // value @ 234496
        }
    }
}

// ============================================================
extern "C" void kernel_launch(void* const* d_in, const int* in_sizes, int n_in,
                              void* d_out, int out_size)
{
    const float* has   = (const float*)d_in[0];
    const float* z     = (const float*)d_in[1];
    const float* dz    = (const float*)d_in[2];
    const unsigned char* adj = (const unsigned char*)d_in[3];
    const float* Wih_f = (const float*)d_in[4];
    const float* Whh_f = (const float*)d_in[5];
    const float* bih_f = (const float*)d_in[6];
    const float* bhh_f = (const float*)d_in[7];
    const float* Wih_b = (const float*)d_in[8];
    const float* Whh_b = (const float*)d_in[9];
    const float* bih_b = (const float*)d_in[10];
    const float* bhh_b = (const float*)d_in[11];
    const float* Wf    = (const float*)d_in[12];
    const float* bf    = (const float*)d_in[13];
    const float* Wb    = (const float*)d_in[14];
    const float* bb    = (const float*)d_in[15];
    const float* Wa    = (const float*)d_in[16];
    const float* ba    = (const float*)d_in[17];
    const float* Wc    = (const float*)d_in[18];
    const float* bc    = (const float*)d_in[19];
    const float* Wu    = (const float*)d_in[20];
    const float* bu    = (const float*)d_in[21];
    float* out = (float*)d_out;

    const size_t smem = SMEM_FLOATS * sizeof(float);   // ~139 KB -> 1 block/SM
    cudaFuncSetAttribute(k_scan, cudaFuncAttributeMaxDynamicSharedMemorySize, (int)smem);

    k_scan<<<128, TPB, smem>>>(adj, has, z, dz,
                               Wih_f, Whh_f, bih_f, bhh_f,
                               Wih_b, Whh_b, bih_b, bhh_b,
                               Wf, bf, Wb, bb);
    k_heads<<<144, 256>>>(has, Wu, bu, Wa, ba, Wc, bc, out);
}